// round 2
// baseline (speedup 1.0000x reference)
#include <cuda_runtime.h>

#define NN 50000
#define EE 800000
#define INF 128
#define HC 128
#define HH 8
#define ED 16

// ---- scratch (device globals; no allocation allowed) ----
__device__ __align__(16) float g_q[NN * HC];
__device__ __align__(16) float g_k[NN * HC];
__device__ __align__(16) float g_v[NN * HC];
__device__ __align__(16) float g_p[EE * HH];
__device__ __align__(16) float g_sum[NN * HH];

// ---------------------------------------------------------------------------
// zero the per-(node,head) softmax denominators (graph replays need this)
// ---------------------------------------------------------------------------
__global__ void zero_sum_kernel() {
    int i = blockIdx.x * blockDim.x + threadIdx.x;
    if (i < NN * HH) g_sum[i] = 0.f;
}

// ---------------------------------------------------------------------------
// Fused 4x GEMM: y = x @ W + b for W in {w_q, w_k, w_v, w_skip}
// blockIdx.y selects the matrix; skip result goes straight into d_out.
// Tile: M=128, N=128, K chunked by 32. 256 threads, 8x8 microtile/thread.
// ---------------------------------------------------------------------------
__global__ __launch_bounds__(256) void gemm_kernel(
    const float* __restrict__ x,
    const float* __restrict__ wq, const float* __restrict__ bq,
    const float* __restrict__ wk, const float* __restrict__ bk,
    const float* __restrict__ wv, const float* __restrict__ bv,
    const float* __restrict__ ws, const float* __restrict__ bs,
    float* __restrict__ out)
{
    __shared__ float As[32][132];   // transposed x tile: As[k][m], padded
    __shared__ float Bs[32][128];   // Bs[k][n]

    const float* W; const float* B; float* O;
    switch (blockIdx.y) {
        case 0:  W = wq; B = bq; O = g_q; break;
        case 1:  W = wk; B = bk; O = g_k; break;
        case 2:  W = wv; B = bv; O = g_v; break;
        default: W = ws; B = bs; O = out; break;
    }

    int tid = threadIdx.x;
    int tx = tid & 15, ty = tid >> 4;
    int rowBase = blockIdx.x * 128;

    float acc[8][8];
    #pragma unroll
    for (int i = 0; i < 8; i++)
        #pragma unroll
        for (int j = 0; j < 8; j++) acc[i][j] = 0.f;

    for (int k0 = 0; k0 < INF; k0 += 32) {
        #pragma unroll
        for (int i = 0; i < 16; i++) {
            int idx = tid + i * 256;       // 0..4095
            int r  = idx >> 5;             // row within tile
            int kk = idx & 31;             // k within chunk
            int gr = rowBase + r;
            As[kk][r] = (gr < NN) ? x[gr * INF + k0 + kk] : 0.f;
        }
        #pragma unroll
        for (int i = 0; i < 16; i++) {
            int idx = tid + i * 256;
            int kk = idx >> 7;
            int n  = idx & 127;
            Bs[kk][n] = W[(k0 + kk) * HC + n];
        }
        __syncthreads();

        #pragma unroll
        for (int kk = 0; kk < 32; kk++) {
            float4 a0 = *(const float4*)&As[kk][ty * 8];
            float4 a1 = *(const float4*)&As[kk][ty * 8 + 4];
            float4 b0 = *(const float4*)&Bs[kk][tx * 8];
            float4 b1 = *(const float4*)&Bs[kk][tx * 8 + 4];
            float av[8] = {a0.x, a0.y, a0.z, a0.w, a1.x, a1.y, a1.z, a1.w};
            float bw[8] = {b0.x, b0.y, b0.z, b0.w, b1.x, b1.y, b1.z, b1.w};
            #pragma unroll
            for (int i = 0; i < 8; i++)
                #pragma unroll
                for (int j = 0; j < 8; j++)
                    acc[i][j] += av[i] * bw[j];
        }
        __syncthreads();
    }

    #pragma unroll
    for (int i = 0; i < 8; i++) {
        int gr = rowBase + ty * 8 + i;
        if (gr < NN) {
            #pragma unroll
            for (int j = 0; j < 8; j += 4) {
                float4 o;
                o.x = acc[i][j + 0] + B[tx * 8 + j + 0];
                o.y = acc[i][j + 1] + B[tx * 8 + j + 1];
                o.z = acc[i][j + 2] + B[tx * 8 + j + 2];
                o.w = acc[i][j + 3] + B[tx * 8 + j + 3];
                *(float4*)&O[gr * HC + tx * 8 + j] = o;
            }
        }
    }
}

// ---------------------------------------------------------------------------
// Edge pass 1: one warp per edge (grid-stride).
// edge_index is int32 on device (JAX x64 disabled -> int64 request becomes
// int32). Layout [2, E]: src = ei[e], dst = ei[E + e].
// Recompute e = edge_attr @ w_e in registers (w_e in smem), compute
// alpha_h = q[dst,h]·(k[src,h]+e_h)/4, p = exp(alpha) (softmax shift-invariant,
// alpha is O(1) bounded -> max subtraction unnecessary), store p,
// accumulate per-(dst,head) denominator.
// ---------------------------------------------------------------------------
__global__ __launch_bounds__(256) void edge_pass1(
    const int* __restrict__ ei,
    const float* __restrict__ ea,
    const float* __restrict__ we)
{
    __shared__ float swe[ED * HC];
    for (int i = threadIdx.x; i < ED * HC; i += 256) swe[i] = we[i];
    __syncthreads();

    int lane = threadIdx.x & 31;
    int gw = (blockIdx.x * 256 + threadIdx.x) >> 5;
    int nw = (gridDim.x * 256) >> 5;
    int c0 = lane << 2;        // 4 channels per lane
    int head = lane >> 2;      // 4 lanes per head (C=16)

    for (int e = gw; e < EE; e += nw) {
        int src = ei[e];
        int dst = ei[EE + e];

        float mea = (lane < ED) ? ea[e * ED + lane] : 0.f;
        float ex = 0.f, ey = 0.f, ez = 0.f, ew = 0.f;
        #pragma unroll
        for (int i = 0; i < ED; i++) {
            float a = __shfl_sync(0xffffffffu, mea, i);
            float4 w4 = *(const float4*)&swe[i * HC + c0];
            ex += a * w4.x; ey += a * w4.y; ez += a * w4.z; ew += a * w4.w;
        }

        float4 q4 = *(const float4*)&g_q[dst * HC + c0];
        float4 k4 = *(const float4*)&g_k[src * HC + c0];
        float s = q4.x * (k4.x + ex) + q4.y * (k4.y + ey)
                + q4.z * (k4.z + ez) + q4.w * (k4.w + ew);
        s += __shfl_xor_sync(0xffffffffu, s, 1);
        s += __shfl_xor_sync(0xffffffffu, s, 2);

        float p = __expf(s * 0.25f);   // 1/sqrt(C), C=16
        if ((lane & 3) == 0) {
            g_p[e * HH + head] = p;
            atomicAdd(&g_sum[dst * HH + head], p);
        }
    }
}

// ---------------------------------------------------------------------------
// Edge pass 2: msg = (v[src]+e) * p / (sum+1e-16), vector-reduced into out.
// ---------------------------------------------------------------------------
__global__ __launch_bounds__(256) void edge_pass2(
    const int* __restrict__ ei,
    const float* __restrict__ ea,
    const float* __restrict__ we,
    float* __restrict__ out)
{
    __shared__ float swe[ED * HC];
    for (int i = threadIdx.x; i < ED * HC; i += 256) swe[i] = we[i];
    __syncthreads();

    int lane = threadIdx.x & 31;
    int gw = (blockIdx.x * 256 + threadIdx.x) >> 5;
    int nw = (gridDim.x * 256) >> 5;
    int c0 = lane << 2;
    int head = lane >> 2;

    for (int e = gw; e < EE; e += nw) {
        int src = ei[e];
        int dst = ei[EE + e];

        float mea = (lane < ED) ? ea[e * ED + lane] : 0.f;
        float ex = 0.f, ey = 0.f, ez = 0.f, ew = 0.f;
        #pragma unroll
        for (int i = 0; i < ED; i++) {
            float a = __shfl_sync(0xffffffffu, mea, i);
            float4 w4 = *(const float4*)&swe[i * HC + c0];
            ex += a * w4.x; ey += a * w4.y; ez += a * w4.z; ew += a * w4.w;
        }

        float4 v4 = *(const float4*)&g_v[src * HC + c0];
        float p = g_p[e * HH + head];
        float ssum = g_sum[dst * HH + head];
        float w = p / (ssum + 1e-16f);

        float mx = (v4.x + ex) * w;
        float my = (v4.y + ey) * w;
        float mz = (v4.z + ez) * w;
        float mw = (v4.w + ew) * w;

        float* op = out + (size_t)dst * HC + c0;
        asm volatile("red.global.add.v4.f32 [%0], {%1, %2, %3, %4};"
                     :: "l"(op), "f"(mx), "f"(my), "f"(mz), "f"(mw)
                     : "memory");
    }
}

// ---------------------------------------------------------------------------
extern "C" void kernel_launch(void* const* d_in, const int* in_sizes, int n_in,
                              void* d_out, int out_size)
{
    const float* x  = (const float*)d_in[0];
    const int*   ei = (const int*)d_in[1];
    const float* ea = (const float*)d_in[2];
    const float* wq = (const float*)d_in[3];
    const float* bq = (const float*)d_in[4];
    const float* wk = (const float*)d_in[5];
    const float* bk = (const float*)d_in[6];
    const float* wv = (const float*)d_in[7];
    const float* bv = (const float*)d_in[8];
    const float* we = (const float*)d_in[9];
    const float* ws = (const float*)d_in[10];
    const float* bs = (const float*)d_in[11];
    float* out = (float*)d_out;

    zero_sum_kernel<<<(NN * HH + 255) / 256, 256>>>();

    dim3 g0(391, 4);                       // ceil(50000/128) x 4 matrices
    gemm_kernel<<<g0, 256>>>(x, wq, bq, wk, bk, wv, bv, ws, bs, out);

    edge_pass1<<<2048, 256>>>(ei, ea, we);
    edge_pass2<<<2048, 256>>>(ei, ea, we, out);
}

// round 3
// speedup vs baseline: 1.2331x; 1.2331x over previous
#include <cuda_runtime.h>

#define NN 50000
#define EE 800000
#define INF 128
#define HC 128
#define HH 8
#define ED 16

// ---- scratch (device globals; no allocation allowed) ----
__device__ __align__(16) float g_q[NN * HC];
__device__ __align__(16) float g_k[NN * HC];
__device__ __align__(16) float g_v[NN * HC];
__device__ __align__(16) float g_attn[NN * HC];   // unnormalized numerator
__device__ __align__(16) float g_sum[NN * HH];    // softmax denominator

// ---------------------------------------------------------------------------
// zero numerator + denominator (graph replays need this every call)
// ---------------------------------------------------------------------------
__global__ void zero_kernel() {
    int i = blockIdx.x * blockDim.x + threadIdx.x;
    int n4 = (NN * HC) / 4;
    if (i < n4) ((float4*)g_attn)[i] = make_float4(0.f, 0.f, 0.f, 0.f);
    if (i < NN * HH) g_sum[i] = 0.f;
}

// ---------------------------------------------------------------------------
// Fused 4x GEMM: y = x @ W + b for W in {w_q, w_k, w_v, w_skip}
// blockIdx.y selects the matrix; skip result goes straight into d_out.
// Tile: M=128, N=128, K chunked by 32. 256 threads, 8x8 microtile/thread.
// ---------------------------------------------------------------------------
__global__ __launch_bounds__(256) void gemm_kernel(
    const float* __restrict__ x,
    const float* __restrict__ wq, const float* __restrict__ bq,
    const float* __restrict__ wk, const float* __restrict__ bk,
    const float* __restrict__ wv, const float* __restrict__ bv,
    const float* __restrict__ ws, const float* __restrict__ bs,
    float* __restrict__ out)
{
    __shared__ float As[32][132];   // transposed x tile: As[k][m], padded
    __shared__ float Bs[32][128];   // Bs[k][n]

    const float* W; const float* B; float* O;
    switch (blockIdx.y) {
        case 0:  W = wq; B = bq; O = g_q; break;
        case 1:  W = wk; B = bk; O = g_k; break;
        case 2:  W = wv; B = bv; O = g_v; break;
        default: W = ws; B = bs; O = out; break;
    }

    int tid = threadIdx.x;
    int tx = tid & 15, ty = tid >> 4;
    int rowBase = blockIdx.x * 128;

    float acc[8][8];
    #pragma unroll
    for (int i = 0; i < 8; i++)
        #pragma unroll
        for (int j = 0; j < 8; j++) acc[i][j] = 0.f;

    for (int k0 = 0; k0 < INF; k0 += 32) {
        #pragma unroll
        for (int i = 0; i < 16; i++) {
            int idx = tid + i * 256;       // 0..4095
            int r  = idx >> 5;             // row within tile
            int kk = idx & 31;             // k within chunk
            int gr = rowBase + r;
            As[kk][r] = (gr < NN) ? x[gr * INF + k0 + kk] : 0.f;
        }
        #pragma unroll
        for (int i = 0; i < 16; i++) {
            int idx = tid + i * 256;
            int kk = idx >> 7;
            int n  = idx & 127;
            Bs[kk][n] = W[(k0 + kk) * HC + n];
        }
        __syncthreads();

        #pragma unroll
        for (int kk = 0; kk < 32; kk++) {
            float4 a0 = *(const float4*)&As[kk][ty * 8];
            float4 a1 = *(const float4*)&As[kk][ty * 8 + 4];
            float4 b0 = *(const float4*)&Bs[kk][tx * 8];
            float4 b1 = *(const float4*)&Bs[kk][tx * 8 + 4];
            float av[8] = {a0.x, a0.y, a0.z, a0.w, a1.x, a1.y, a1.z, a1.w};
            float bw[8] = {b0.x, b0.y, b0.z, b0.w, b1.x, b1.y, b1.z, b1.w};
            #pragma unroll
            for (int i = 0; i < 8; i++)
                #pragma unroll
                for (int j = 0; j < 8; j++)
                    acc[i][j] += av[i] * bw[j];
        }
        __syncthreads();
    }

    #pragma unroll
    for (int i = 0; i < 8; i++) {
        int gr = rowBase + ty * 8 + i;
        if (gr < NN) {
            #pragma unroll
            for (int j = 0; j < 8; j += 4) {
                float4 o;
                o.x = acc[i][j + 0] + B[tx * 8 + j + 0];
                o.y = acc[i][j + 1] + B[tx * 8 + j + 1];
                o.z = acc[i][j + 2] + B[tx * 8 + j + 2];
                o.w = acc[i][j + 3] + B[tx * 8 + j + 3];
                *(float4*)&O[gr * HC + tx * 8 + j] = o;
            }
        }
    }
}

// ---------------------------------------------------------------------------
// Single fused edge pass: one warp per edge (grid-stride), 4 channels/lane.
//   e   = edge_attr[e] @ w_e        (w_e slice held in REGISTERS, loop-inv)
//   p   = exp(q[dst]·(k[src]+e)/4)  (softmax shift-invariant, alpha bounded)
//   den[dst,h]  += p                (scalar red)
//   num[dst,:]  += p*(v[src]+e)     (red.global.add.v4)
// Normalization deferred to node-level kernel: num/(den+eps) == softmax agg.
// ---------------------------------------------------------------------------
__global__ __launch_bounds__(256) void edge_kernel(
    const int* __restrict__ ei,
    const float* __restrict__ ea,
    const float* __restrict__ we)
{
    int lane = threadIdx.x & 31;
    int gw = (blockIdx.x * 256 + threadIdx.x) >> 5;
    int nw = (gridDim.x * 256) >> 5;
    int c0 = lane << 2;        // 4 channels per lane
    int head = lane >> 2;      // 4 lanes per head (C=16)

    // loop-invariant w_e slice: 16 x float4 in registers (coalesced load)
    float4 rw[ED];
    #pragma unroll
    for (int i = 0; i < ED; i++)
        rw[i] = *(const float4*)&we[i * HC + c0];

    for (int e = gw; e < EE; e += nw) {
        int src = ei[e];
        int dst = ei[EE + e];

        float mea = (lane < ED) ? ea[e * ED + lane] : 0.f;
        float ex = 0.f, ey = 0.f, ez = 0.f, ew = 0.f;
        #pragma unroll
        for (int i = 0; i < ED; i++) {
            float a = __shfl_sync(0xffffffffu, mea, i);
            ex += a * rw[i].x; ey += a * rw[i].y;
            ez += a * rw[i].z; ew += a * rw[i].w;
        }

        float4 q4 = *(const float4*)&g_q[dst * HC + c0];
        float4 k4 = *(const float4*)&g_k[src * HC + c0];
        float s = q4.x * (k4.x + ex) + q4.y * (k4.y + ey)
                + q4.z * (k4.z + ez) + q4.w * (k4.w + ew);
        s += __shfl_xor_sync(0xffffffffu, s, 1);
        s += __shfl_xor_sync(0xffffffffu, s, 2);

        float p = __expf(s * 0.25f);   // 1/sqrt(C), C=16

        if ((lane & 3) == 0) {
            float* dp = &g_sum[dst * HH + head];
            asm volatile("red.global.add.f32 [%0], %1;" :: "l"(dp), "f"(p) : "memory");
        }

        float4 v4 = *(const float4*)&g_v[src * HC + c0];
        float mx = (v4.x + ex) * p;
        float my = (v4.y + ey) * p;
        float mz = (v4.z + ez) * p;
        float mw = (v4.w + ew) * p;

        float* op = g_attn + (size_t)dst * HC + c0;
        asm volatile("red.global.add.v4.f32 [%0], {%1, %2, %3, %4};"
                     :: "l"(op), "f"(mx), "f"(my), "f"(mz), "f"(mw)
                     : "memory");
    }
}

// ---------------------------------------------------------------------------
// Node-level normalize: out += num / (den + 1e-16). One float4 per thread.
// ---------------------------------------------------------------------------
__global__ __launch_bounds__(256) void normalize_kernel(float* __restrict__ out)
{
    int i = blockIdx.x * blockDim.x + threadIdx.x;   // float4 index
    int n4 = (NN * HC) / 4;
    if (i >= n4) return;
    int node = i >> 5;                // 32 float4 per node
    int head = (i & 31) >> 2;         // 4 float4 per head
    float inv = 1.f / (g_sum[node * HH + head] + 1e-16f);
    float4 a = ((const float4*)g_attn)[i];
    float4 o = ((float4*)out)[i];
    o.x += a.x * inv; o.y += a.y * inv;
    o.z += a.z * inv; o.w += a.w * inv;
    ((float4*)out)[i] = o;
}

// ---------------------------------------------------------------------------
extern "C" void kernel_launch(void* const* d_in, const int* in_sizes, int n_in,
                              void* d_out, int out_size)
{
    const float* x  = (const float*)d_in[0];
    const int*   ei = (const int*)d_in[1];
    const float* ea = (const float*)d_in[2];
    const float* wq = (const float*)d_in[3];
    const float* bq = (const float*)d_in[4];
    const float* wk = (const float*)d_in[5];
    const float* bk = (const float*)d_in[6];
    const float* wv = (const float*)d_in[7];
    const float* bv = (const float*)d_in[8];
    const float* we = (const float*)d_in[9];
    const float* ws = (const float*)d_in[10];
    const float* bs = (const float*)d_in[11];
    float* out = (float*)d_out;

    zero_kernel<<<((NN * HC) / 4 + 255) / 256, 256>>>();

    dim3 g0(391, 4);                       // ceil(50000/128) x 4 matrices
    gemm_kernel<<<g0, 256>>>(x, wq, bq, wk, bk, wv, bv, ws, bs, out);

    edge_kernel<<<2048, 256>>>(ei, ea, we);

    normalize_kernel<<<((NN * HC) / 4 + 255) / 256, 256>>>(out);
}